// round 9
// baseline (speedup 1.0000x reference)
#include <cuda_runtime.h>
#include <math.h>

#define N_PCD 5000
#define N_RGB 15000
#define NTOT  20000
#define NPAD  20480
#define NA    4096
#define SA_NS 32
#define NB_K  64
#define K1    163
#define NROWS (NA*SA_NS)

// ---------------- static device scratch ----------------
__device__ float g_xs[NPAD], g_ys[NPAD], g_zs[NPAD];
__device__ float g_ax[NA], g_ay[NA], g_az[NA];
__device__ int   g_fidx[NA];
__device__ int   g_nb[NA*SA_NS];
__device__ float g_rgbT[(size_t)N_RGB*128];
__device__ float g_W1T[K1*128];
__device__ float g_W2T[128*128];
__device__ float g_W3T[128*128];
__device__ float g_fpW1T[160*128];
__device__ float g_fpW2T[128*32];
__device__ float g_G [(size_t)NROWS*K1];
__device__ float g_H1[(size_t)NROWS*128];
__device__ float g_H2[(size_t)NROWS*128];
__device__ float g_saf[NA*128];
__device__ int   g_nn[N_PCD*3];
__device__ float g_wg[N_PCD*3];
__device__ float g_fpf[N_PCD*32];
__device__ int   g_nb2[N_PCD*NB_K];
__device__ unsigned int g_gmax;

// (dx*dx + dy*dy) + dz*dz, contraction forbidden (FMA could flip argmax/top-k ties)
__device__ __forceinline__ float sqdist(float ax, float ay, float az,
                                        float bx, float by, float bz) {
  float dx = __fadd_rn(ax, -bx);
  float dy = __fadd_rn(ay, -by);
  float dz = __fadd_rn(az, -bz);
  return __fadd_rn(__fadd_rn(__fmul_rn(dx,dx), __fmul_rn(dy,dy)), __fmul_rn(dz,dz));
}

// ---------------- prep: SoA xyz (padded), reset gmax ----------------
__global__ void k_build(const float* __restrict__ pcd_xyz,
                        const float* __restrict__ rgb_xyz) {
  int i = blockIdx.x*blockDim.x + threadIdx.x;
  if (i == 0) g_gmax = 0u;
  if (i >= NPAD) return;
  float x=0.f, y=0.f, z=0.f;
  if (i < N_PCD)      { x=pcd_xyz[i*3]; y=pcd_xyz[i*3+1]; z=pcd_xyz[i*3+2]; }
  else if (i < NTOT)  { int j=i-N_PCD; x=rgb_xyz[j*3]; y=rgb_xyz[j*3+1]; z=rgb_xyz[j*3+2]; }
  g_xs[i]=x; g_ys[i]=y; g_zs[i]=z;
}

// ---------------- transposes into device globals ----------------
__global__ void k_transpose(int which, const float* __restrict__ W) {
  float* WT; int N, K, stride;
  switch (which) {
    case 0: WT=g_W1T;   N=128; K=163;   stride=163;   break;
    case 1: WT=g_W2T;   N=128; K=128;   stride=128;   break;
    case 2: WT=g_W3T;   N=128; K=128;   stride=128;   break;
    case 3: WT=g_fpW1T; N=128; K=160;   stride=288;   break; // cols>=160 multiply zeros
    case 4: WT=g_fpW2T; N=32;  K=128;   stride=128;   break;
    default:WT=g_rgbT;  N=128; K=15000; stride=15000; break; // rgb_features[0].T
  }
  int idx = blockIdx.x*blockDim.x + threadIdx.x;
  if (idx >= N*K) return;
  int k = idx / N, n = idx - k*N;
  WT[idx] = W[(size_t)n*stride + k];
}

// ---------------- FPS: single persistent block; x,y in smem, z+d in regs ----------------
__global__ void __launch_bounds__(1024, 1) k_fps() {
  extern __shared__ float sh[];
  float* shx = sh;
  float* shy = sh + NPAD;
  __shared__ float s_val[32];
  __shared__ int   s_idx[32];
  __shared__ float s_c[3];
  int t = threadIdx.x;
  for (int i = t; i < NPAD; i += 1024) { shx[i] = g_xs[i]; shy[i] = g_ys[i]; }
  float d[20], z[20];
#pragma unroll
  for (int k = 0; k < 20; k++) {
    int i = k*1024 + t;
    z[k] = g_zs[i];
    d[k] = (i < NTOT) ? 1e10f : -1.0f;
  }
  if (t == 0) {
    g_fidx[0] = 0;
    s_c[0]=g_xs[0]; s_c[1]=g_ys[0]; s_c[2]=g_zs[0];
    g_ax[0]=s_c[0]; g_ay[0]=s_c[1]; g_az[0]=s_c[2];
  }
  __syncthreads();
  for (int step = 1; step < NA; step++) {
    float lx = s_c[0], ly = s_c[1], lz = s_c[2];
    float best = -1e30f; int bidx = 0;
#pragma unroll
    for (int k = 0; k < 20; k++) {
      int i = k*1024 + t;
      float dd = sqdist(shx[i], shy[i], z[k], lx, ly, lz);
      dd = fminf(d[k], dd);
      d[k] = dd;
      if (dd > best) { best = dd; bidx = i; }   // ascending i: first max kept
    }
#pragma unroll
    for (int off = 16; off; off >>= 1) {
      float v = __shfl_down_sync(0xffffffffu, best, off);
      int   j = __shfl_down_sync(0xffffffffu, bidx, off);
      if (v > best || (v == best && j < bidx)) { best = v; bidx = j; }
    }
    if ((t & 31) == 0) { s_val[t>>5] = best; s_idx[t>>5] = bidx; }
    __syncthreads();
    if (t < 32) {
      best = s_val[t]; bidx = s_idx[t];
#pragma unroll
      for (int off = 16; off; off >>= 1) {
        float v = __shfl_down_sync(0xffffffffu, best, off);
        int   j = __shfl_down_sync(0xffffffffu, bidx, off);
        if (v > best || (v == best && j < bidx)) { best = v; bidx = j; }
      }
      if (t == 0) {
        g_fidx[step] = bidx;
        float cx = shx[bidx], cy = shy[bidx], cz = g_zs[bidx];
        s_c[0]=cx; s_c[1]=cy; s_c[2]=cz;
        g_ax[step]=cx; g_ay[step]=cy; g_az[step]=cz;
      }
    }
    __syncthreads();
  }
}

// ---------------- ball query: first-k in-radius by INDEX, pad with first ----------------
__global__ void k_ballq(int mode) {
  int w    = (blockIdx.x*blockDim.x + threadIdx.x) >> 5;
  int lane = threadIdx.x & 31;
  int npoints, ks; float r2, cx, cy, cz; int* row;
  if (mode == 0) {
    if (w >= NA) return;
    npoints = NTOT; ks = SA_NS; r2 = 0.01f;       // f32(0.1*0.1)
    cx = g_ax[w]; cy = g_ay[w]; cz = g_az[w];
    row = g_nb + (size_t)w*SA_NS;
  } else {
    if (w >= N_PCD) return;
    npoints = N_PCD; ks = NB_K; r2 = 0.04f;       // f32(0.2*0.2)
    cx = g_xs[w]; cy = g_ys[w]; cz = g_zs[w];
    row = g_nb2 + (size_t)w*NB_K;
  }
  int cnt = 0;
  for (int base = 0; base < npoints && cnt < ks; base += 32) {
    int i = base + lane;
    bool in = false;
    if (i < npoints) {
      float dd = sqdist(g_xs[i], g_ys[i], g_zs[i], cx, cy, cz);
      in = dd < r2;
    }
    unsigned m = __ballot_sync(0xffffffffu, in);
    if (m) {
      int rank = __popc(m & ((1u << lane) - 1u));
      int pos  = cnt + rank;
      if (in && pos < ks) row[pos] = i;
      cnt += __popc(m);
    }
  }
  __syncwarp();
  if (cnt < ks) {               // center always in-radius -> cnt >= 1
    int first = row[0];
    for (int j = cnt + lane; j < ks; j += 32) row[j] = first;
  }
}

// ---------------- gather G = [gxyz | pcd_feat | rgb_feat] ----------------
__global__ void k_gather(const float* __restrict__ pcd_feat) {
  int r = blockIdx.x;
  int t = threadIdx.x;
  if (t >= K1) return;
  int a = r >> 5;
  int p = g_nb[r];
  float v;
  if (t < 3) {
    float pc = (t == 0) ? g_xs[p] : (t == 1) ? g_ys[p] : g_zs[p];
    float ac = (t == 0) ? g_ax[a] : (t == 1) ? g_ay[a] : g_az[a];
    v = __fadd_rn(pc, -ac) / 0.1f;
  } else if (t < 35) {
    v = (p < N_PCD) ? pcd_feat[p*32 + (t-3)] : 0.f;
  } else {
    v = (p >= N_PCD) ? g_rgbT[(size_t)(p - N_PCD)*128 + (t-35)] : 0.f;
  }
  g_G[(size_t)r*K1 + t] = v;
}

// ---------------- SGEMM + bias + relu: M=131072, N=128 ----------------
__global__ void __launch_bounds__(256, 2)
k_gemm(int layer, const float* __restrict__ b1,
       const float* __restrict__ b2, const float* __restrict__ b3) {
  const float* A; const float* Bt; const float* bias; float* C; int K;
  if (layer == 0)      { A=g_G;  Bt=g_W1T; bias=b1; C=g_H1; K=K1;  }
  else if (layer == 1) { A=g_H1; Bt=g_W2T; bias=b2; C=g_H2; K=128; }
  else                 { A=g_H2; Bt=g_W3T; bias=b3; C=g_H1; K=128; }

  __shared__ float As[8*132];
  __shared__ float Bs[8*128];
  int t  = threadIdx.x;
  int m0 = blockIdx.x * 128;
  int ty = t >> 4, tx = t & 15;
  float acc[8][8];
#pragma unroll
  for (int r = 0; r < 8; r++)
#pragma unroll
    for (int c = 0; c < 8; c++) acc[r][c] = 0.f;

  for (int k0 = 0; k0 < K; k0 += 8) {
#pragma unroll
    for (int i = 0; i < 4; i++) {
      int idx = t + i*256;
      int ml = idx >> 3, kk = idx & 7;
      int kg = k0 + kk;
      As[kk*132 + ml] = (kg < K) ? A[(size_t)(m0+ml)*K + kg] : 0.f;
    }
#pragma unroll
    for (int i = 0; i < 4; i++) {
      int idx = t + i*256;
      int kk = idx >> 7, n = idx & 127;
      int kg = k0 + kk;
      Bs[kk*128 + n] = (kg < K) ? Bt[(size_t)kg*128 + n] : 0.f;
    }
    __syncthreads();
#pragma unroll
    for (int kk = 0; kk < 8; kk++) {
      float4 a0 = *(const float4*)&As[kk*132 + ty*8];
      float4 a1 = *(const float4*)&As[kk*132 + ty*8 + 4];
      float4 b0 = *(const float4*)&Bs[kk*128 + tx*8];
      float4 b1 = *(const float4*)&Bs[kk*128 + tx*8 + 4];
      float a[8] = {a0.x,a0.y,a0.z,a0.w,a1.x,a1.y,a1.z,a1.w};
      float b[8] = {b0.x,b0.y,b0.z,b0.w,b1.x,b1.y,b1.z,b1.w};
#pragma unroll
      for (int r = 0; r < 8; r++)
#pragma unroll
        for (int c = 0; c < 8; c++) acc[r][c] = fmaf(a[r], b[c], acc[r][c]);
    }
    __syncthreads();
  }
#pragma unroll
  for (int r = 0; r < 8; r++) {
    int m = m0 + ty*8 + r;
#pragma unroll
    for (int c = 0; c < 8; c++) {
      int n = tx*8 + c;
      float v = acc[r][c] + bias[n];
      C[(size_t)m*128 + n] = v > 0.f ? v : 0.f;
    }
  }
}

__global__ void k_maxpool() {
  int a = blockIdx.x, c = threadIdx.x;
  const float* base = g_H1 + (size_t)a*SA_NS*128 + c;
  float m = base[0];
#pragma unroll 4
  for (int s = 1; s < SA_NS; s++) m = fmaxf(m, base[(size_t)s*128]);
  g_saf[a*128 + c] = m;
}

// ---------------- 3-NN among anchors + inverse-distance weights (pcd rows only) ----------------
__global__ void k_nn3() {
  int i = blockIdx.x*blockDim.x + threadIdx.x;
  if (i >= N_PCD) return;
  float px = g_xs[i], py = g_ys[i], pz = g_zs[i];
  float d0 = 1e30f, d1 = 1e30f, d2 = 1e30f;
  int   i0 = 0, i1 = 0, i2 = 0;
  for (int a = 0; a < NA; a++) {
    float dd = sqdist(px, py, pz, g_ax[a], g_ay[a], g_az[a]);
    if (dd < d2) {                 // strict: earlier index wins ties (lax.top_k stable)
      if (dd < d1) {
        d2 = d1; i2 = i1;
        if (dd < d0) { d1 = d0; i1 = i0; d0 = dd; i0 = a; }
        else         { d1 = dd; i1 = a; }
      } else { d2 = dd; i2 = a; }
    }
  }
  float w0 = 1.0f/(d0 + 1e-8f), w1 = 1.0f/(d1 + 1e-8f), w2 = 1.0f/(d2 + 1e-8f);
  float ws = (w0 + w1) + w2;
  g_nn[i*3+0]=i0; g_nn[i*3+1]=i1; g_nn[i*3+2]=i2;
  g_wg[i*3+0]=w0/ws; g_wg[i*3+1]=w1/ws; g_wg[i*3+2]=w2/ws;
}

// ---------------- fused FP MLP (5000 pcd rows; effective K=160) ----------------
__global__ void k_fp(const float* __restrict__ pcd_feat,
                     const float* __restrict__ b1, const float* __restrict__ b2,
                     float* __restrict__ out_vf) {
  __shared__ float s_in[128];
  __shared__ float s_pf[32];
  __shared__ float s_h[128];
  int n = blockIdx.x, t = threadIdx.x;
  int i0 = g_nn[n*3+0], i1 = g_nn[n*3+1], i2 = g_nn[n*3+2];
  float w0 = g_wg[n*3+0], w1 = g_wg[n*3+1], w2 = g_wg[n*3+2];
  s_in[t] = w0*g_saf[i0*128+t] + w1*g_saf[i1*128+t] + w2*g_saf[i2*128+t];
  if (t < 32) s_pf[t] = pcd_feat[n*32 + t];
  __syncthreads();
  float acc = b1[t];
#pragma unroll 8
  for (int k = 0; k < 128; k++) acc = fmaf(s_in[k], g_fpW1T[k*128 + t], acc);
#pragma unroll 8
  for (int k = 0; k < 32; k++)  acc = fmaf(s_pf[k], g_fpW1T[(128+k)*128 + t], acc);
  s_h[t] = acc > 0.f ? acc : 0.f;
  __syncthreads();
  if (t < 32) {
    float a2 = b2[t];
#pragma unroll 8
    for (int k = 0; k < 128; k++) a2 = fmaf(s_h[k], g_fpW2T[k*32 + t], a2);
    float v = a2 > 0.f ? a2 : 0.f;
    g_fpf[n*32 + t] = v;
    atomicMax(&g_gmax, __float_as_uint(v));     // relu>=0 -> uint order == float order
    float sq = v*v;
#pragma unroll
    for (int off = 16; off; off >>= 1) sq += __shfl_xor_sync(0xffffffffu, sq, off);
    float nrm = fmaxf(sqrtf(sq), 1e-12f);
    out_vf[n*32 + t] = v / nrm;
  }
}

// ---------------- detection scores ----------------
__global__ void k_det(float* __restrict__ out_scores) {
  int i = blockIdx.x, c = threadIdx.x;   // 32 threads = 32 channels
  const int* nb = g_nb2 + (size_t)i*NB_K;
  float sum = 0.f;
#pragma unroll 4
  for (int j = 0; j < NB_K; j++) sum += g_fpf[nb[j]*32 + c];
  float s = __uint_as_float(g_gmax) + 1e-6f;
  float fi = g_fpf[i*32 + c] / s;
  float mean = (sum * (1.0f/64.0f)) / s;
  float x = fi - mean;
  float lm = fmaxf(x, 0.f) + log1pf(expf(-fabsf(x)));   // softplus
  float dwmax = fi;
#pragma unroll
  for (int off = 16; off; off >>= 1) dwmax = fmaxf(dwmax, __shfl_xor_sync(0xffffffffu, dwmax, off));
  float sc = lm * (fi / (1e-6f + dwmax));
#pragma unroll
  for (int off = 16; off; off >>= 1) sc = fmaxf(sc, __shfl_xor_sync(0xffffffffu, sc, off));
  if (c == 0) out_scores[i] = sc;
}

__global__ void k_out(const float* __restrict__ pcd_xyz, float* __restrict__ out) {
  int i = blockIdx.x*blockDim.x + threadIdx.x;
  if (i < N_PCD*3) out[i] = pcd_xyz[i];
}

extern "C" void kernel_launch(void* const* d_in, const int* in_sizes, int n_in,
                              void* d_out, int out_size) {
  (void)in_sizes; (void)n_in; (void)out_size;
  const float* pcd_xyz   = (const float*)d_in[0];
  const float* pcd_feat  = (const float*)d_in[1];
  const float* rgb_xyz   = (const float*)d_in[2];
  const float* rgb_feats = (const float*)d_in[3];
  const float* sa_W1 = (const float*)d_in[4];
  const float* sa_b1 = (const float*)d_in[5];
  const float* sa_W2 = (const float*)d_in[6];
  const float* sa_b2 = (const float*)d_in[7];
  const float* sa_W3 = (const float*)d_in[8];
  const float* sa_b3 = (const float*)d_in[9];
  const float* fp_W1 = (const float*)d_in[10];
  const float* fp_b1 = (const float*)d_in[11];
  const float* fp_W2 = (const float*)d_in[12];
  const float* fp_b2 = (const float*)d_in[13];
  float* out = (float*)d_out;
  float* out_scores = out + N_PCD*3;          // 15000..20000
  float* out_vf     = out + N_PCD*3 + N_PCD;  // 20000..180000

  static int smem_set = 0;
  if (!smem_set) {
    cudaFuncSetAttribute(k_fps, cudaFuncAttributeMaxDynamicSharedMemorySize, NPAD*2*sizeof(float));
    smem_set = 1;
  }

  k_build<<<(NPAD+255)/256, 256>>>(pcd_xyz, rgb_xyz);
  k_transpose<<<(128*163+255)/256, 256>>>(0, sa_W1);
  k_transpose<<<(128*128+255)/256, 256>>>(1, sa_W2);
  k_transpose<<<(128*128+255)/256, 256>>>(2, sa_W3);
  k_transpose<<<(128*160+255)/256, 256>>>(3, fp_W1);
  k_transpose<<<(32*128+255)/256, 256>>>(4, fp_W2);
  k_transpose<<<(128*15000+255)/256, 256>>>(5, rgb_feats);

  k_fps<<<1, 1024, NPAD*2*sizeof(float)>>>();
  k_ballq<<<(NA*32+255)/256, 256>>>(0);
  k_gather<<<NROWS, 192>>>(pcd_feat);
  k_gemm<<<NROWS/128, 256>>>(0, sa_b1, sa_b2, sa_b3);
  k_gemm<<<NROWS/128, 256>>>(1, sa_b1, sa_b2, sa_b3);
  k_gemm<<<NROWS/128, 256>>>(2, sa_b1, sa_b2, sa_b3);
  k_maxpool<<<NA, 128>>>();
  k_nn3<<<(N_PCD+255)/256, 256>>>();
  k_fp<<<N_PCD, 128>>>(pcd_feat, fp_b1, fp_b2, out_vf);
  k_ballq<<<(N_PCD*32+255)/256, 256>>>(1);
  k_det<<<N_PCD, 32>>>(out_scores);
  k_out<<<(N_PCD*3+255)/256, 256>>>(pcd_xyz, out);
}